// round 4
// baseline (speedup 1.0000x reference)
#include <cuda_runtime.h>
#include <cuda_fp16.h>
#include <stdint.h>

#define BB 256
#define LL 336
#define NIN 8
#define HH 512
#define PL 96
#define NBE 96
#define NBD 128
#define ASTR 36

__device__ float  g_h0[2][BB*HH];
__device__ float  g_h1[2][BB*HH];
__device__ float  g_c1f[BB*HH];
__device__ float  g_ctx[BB*HH];
__device__ float  g_yprev[BB];
__device__ __half g_enc[(size_t)LL*BB*HH];
__device__ unsigned g_bar_enc, g_bar_dec;

__device__ __forceinline__ float rna_tf32(float x) {
    uint32_t r; asm("cvt.rna.tf32.f32 %0, %1;" : "=r"(r) : "f"(x));
    return __uint_as_float(r);
}
__device__ __forceinline__ float sigf(float x) { return 1.f / (1.f + __expf(-x)); }

__device__ __forceinline__ void gridbar(unsigned* bar, unsigned& round, unsigned nblk) {
    round++;
    __syncthreads();
    __threadfence();
    if (threadIdx.x == 0) {
        unsigned target = round * nblk;
        atomicAdd(bar, 1u);
        while (*(volatile unsigned*)bar < target) { }
        __threadfence();
    }
    __syncthreads();
}

__device__ __forceinline__ void mma_tf32(float c[4], const uint32_t a[4],
                                         uint32_t b0, uint32_t b1) {
    asm volatile(
        "mma.sync.aligned.m16n8k8.row.col.f32.tf32.tf32.f32 "
        "{%0,%1,%2,%3},{%4,%5,%6,%7},{%8,%9},{%0,%1,%2,%3};"
        : "+f"(c[0]), "+f"(c[1]), "+f"(c[2]), "+f"(c[3])
        : "r"(a[0]), "r"(a[1]), "r"(a[2]), "r"(a[3]), "r"(b0), "r"(b1));
}

__device__ __forceinline__ void stage_A(float* dst, const float* __restrict__ src) {
    int t = threadIdx.x;
    int m0 = t >> 3, c4 = (t & 7) * 4;
#pragma unroll
    for (int i = 0; i < 8; i++) {
        int m = m0 + i * 32;
        const float* g = src + (size_t)m * HH + c4;
        unsigned sa = (unsigned)__cvta_generic_to_shared(dst + m * ASTR + c4);
        asm volatile("cp.async.cg.shared.global [%0], [%1], 16;\n" :: "r"(sa), "l"(g));
    }
}
#define CP_COMMIT asm volatile("cp.async.commit_group;\n")
#define CP_WAIT1  asm volatile("cp.async.wait_group 1;\n")
#define CP_WAIT0  asm volatile("cp.async.wait_group 0;\n")

template<int NT>
__device__ __forceinline__ void mma_chunk(const float* __restrict__ As,
                                          const float* __restrict__ Ws, int kb, int wstr,
                                          float (&acc)[2][NT][4], int wbase, int lr, int lc) {
#pragma unroll
    for (int k8 = 0; k8 < 4; k8++) {
        uint32_t a[2][4], b[NT][2];
#pragma unroll
        for (int mi = 0; mi < 2; mi++) {
            const float* ap = As + (wbase + mi * 16 + lr) * ASTR + k8 * 8 + lc;
            a[mi][0] = __float_as_uint(ap[0]);
            a[mi][1] = __float_as_uint(ap[8 * ASTR]);
            a[mi][2] = __float_as_uint(ap[4]);
            a[mi][3] = __float_as_uint(ap[8 * ASTR + 4]);
        }
#pragma unroll
        for (int ni = 0; ni < NT; ni++) {
            const float* bp = Ws + (size_t)(ni * 8 + lr) * wstr + kb + k8 * 8 + lc;
            b[ni][0] = __float_as_uint(bp[0]);
            b[ni][1] = __float_as_uint(bp[4]);
        }
#pragma unroll
        for (int mi = 0; mi < 2; mi++)
#pragma unroll
            for (int ni = 0; ni < NT; ni++)
                mma_tf32(acc[mi][ni], a[mi], b[ni][0], b[ni][1]);
    }
}

template<int NT, int NCH>
__device__ __forceinline__ void gemm_K(const float* __restrict__ srcA,
                                       const float* __restrict__ srcB,
                                       float* As, const float* __restrict__ Ws, int wstr,
                                       float (&acc)[2][NT][4], int wbase, int lr, int lc) {
    stage_A(As, srcA);
    CP_COMMIT;
    for (int kc = 0; kc < NCH; kc++) {
        if (kc + 1 < NCH) {
            const float* s = (kc + 1 < 16 || srcB == nullptr) ? srcA + (kc + 1) * 32
                                                              : srcB + (kc + 1 - 16) * 32;
            stage_A(As + ((kc + 1) & 1) * (256 * ASTR), s);
            CP_COMMIT; CP_WAIT1;
        } else {
            CP_WAIT0;
        }
        __syncthreads();
        mma_chunk<NT>(As + (kc & 1) * (256 * ASTR), Ws, kc * 32, wstr, acc, wbase, lr, lc);
        __syncthreads();
    }
}

__global__ void prep_kernel() {
    int i = blockIdx.x * blockDim.x + threadIdx.x;
    if (i < BB * HH) { g_h0[0][i] = 0.f; g_h1[0][i] = 0.f; }
    if (i == 0) { g_bar_enc = 0u; g_bar_dec = 0u; }
}

// ==================== ENCODER: 96 CTAs, weight-stationary, fused cell ====================
__global__ void __launch_bounds__(256, 1) enc_persistent(
    const float* __restrict__ x, const float* __restrict__ Wih0,
    const float* __restrict__ Whh0, const float* __restrict__ Wih1,
    const float* __restrict__ Whh1,
    const float* __restrict__ bi0, const float* __restrict__ bh0,
    const float* __restrict__ bi1, const float* __restrict__ bh1) {
    extern __shared__ float sm[];
    float* Ws   = sm;            // 33024
    float* As   = sm + 33024;    // 18432
    float* xs   = sm + 51456;    // 2304
    float* bias = sm + 53760;    // 64
    float* w0x  = sm + 53824;    // 512
    int bx = blockIdx.x, tid = threadIdx.x;
    int lane = tid & 31, wid = tid >> 5, lr = lane >> 2, lc = lane & 3;
    int wbase = wid * 32;
    bool L0 = bx < 32;
    int nbase = L0 ? bx * 16 : (bx - 32) * 8;
    int ncols = L0 ? 64 : 32;

    for (int c = wid; c < ncols; c += 8) {
        int gq = (c & 1) | ((c >> 2) & 2);
        int dn = ((c >> 1) & 3) | ((c >> 4) << 2);
        int row = gq * HH + nbase + dn;
        if (L0) {
            for (int k = lane; k < HH; k += 32)
                Ws[c * 516 + k] = rna_tf32(Whh0[(size_t)row * HH + k]);
            if (lane < 8) w0x[c * 8 + lane] = Wih0[row * NIN + lane];
            if (lane == 0) bias[c] = bi0[row] + bh0[row];
        } else {
            for (int k = lane; k < HH; k += 32) {
                Ws[c * 1028 + k]      = rna_tf32(Wih1[(size_t)row * HH + k]);
                Ws[c * 1028 + HH + k] = rna_tf32(Whh1[(size_t)row * HH + k]);
            }
            if (lane == 0) bias[c] = bi1[row] + bh1[row];
        }
    }
    float cst[2][2][4];
#pragma unroll
    for (int a = 0; a < 2; a++)
#pragma unroll
        for (int b = 0; b < 2; b++)
#pragma unroll
            for (int q = 0; q < 4; q++) cst[a][b][q] = 0.f;
    __syncthreads();

    unsigned round = 0;
    for (int s = 0; s <= LL; s++) {
        if (L0) {
            if (s < LL) {
                {   // stage x[:, s, :] slice
                    const float* xp = x + (size_t)tid * (LL * NIN) + (size_t)s * NIN;
#pragma unroll
                    for (int k = 0; k < 8; k++) xs[tid * 9 + k] = xp[k];
                }
                float acc[2][8][4];
#pragma unroll
                for (int a = 0; a < 2; a++)
#pragma unroll
                    for (int b = 0; b < 8; b++)
#pragma unroll
                        for (int q = 0; q < 4; q++) acc[a][b][q] = 0.f;
                gemm_K<8, 16>(g_h0[s & 1], nullptr, As, Ws, 516, acc, wbase, lr, lc);
                float* h0n = g_h0[(s + 1) & 1];
#pragma unroll
                for (int mi = 0; mi < 2; mi++)
#pragma unroll
                    for (int rh = 0; rh < 2; rh++) {
                        int b = wbase + mi * 16 + rh * 8 + lr;
                        const float* xr = xs + b * 9;
#pragma unroll
                        for (int j = 0; j < 4; j++) {
                            int n = nbase + lc + 4 * j;
                            float gv[4];
#pragma unroll
                            for (int gq = 0; gq < 4; gq++) {
                                int ni = 2 * j + (gq >> 1);
                                int cix = ni * 8 + 2 * lc + (gq & 1);
                                float a = acc[mi][ni][rh * 2 + (gq & 1)] + bias[cix];
                                const float* wr = w0x + cix * 8;
#pragma unroll
                                for (int k = 0; k < 8; k++) a += wr[k] * xr[k];
                                gv[gq] = a;
                            }
                            float ig = sigf(gv[0]), fg = sigf(gv[1]);
                            float gg = tanhf(gv[2]), og = sigf(gv[3]);
                            float cc = fg * cst[mi][rh][j] + ig * gg;
                            cst[mi][rh][j] = cc;
                            h0n[(size_t)b * HH + n] = rna_tf32(og * tanhf(cc));
                        }
                    }
            }
        } else {
            if (s >= 1) {
                float acc[2][4][4];
#pragma unroll
                for (int a = 0; a < 2; a++)
#pragma unroll
                    for (int b = 0; b < 4; b++)
#pragma unroll
                        for (int q = 0; q < 4; q++) acc[a][b][q] = 0.f;
                gemm_K<4, 32>(g_h0[s & 1], g_h1[(s + 1) & 1], As, Ws, 1028, acc, wbase, lr, lc);
                float* h1n = g_h1[s & 1];
                __half* ep = g_enc + (size_t)(s - 1) * BB * HH;
#pragma unroll
                for (int mi = 0; mi < 2; mi++)
#pragma unroll
                    for (int rh = 0; rh < 2; rh++) {
                        int b = wbase + mi * 16 + rh * 8 + lr;
#pragma unroll
                        for (int j = 0; j < 2; j++) {
                            int n = nbase + lc + 4 * j;
                            float gv[4];
#pragma unroll
                            for (int gq = 0; gq < 4; gq++) {
                                int ni = 2 * j + (gq >> 1);
                                int cix = ni * 8 + 2 * lc + (gq & 1);
                                gv[gq] = acc[mi][ni][rh * 2 + (gq & 1)] + bias[cix];
                            }
                            float ig = sigf(gv[0]), fg = sigf(gv[1]);
                            float gg = tanhf(gv[2]), og = sigf(gv[3]);
                            float cc = fg * cst[mi][rh][j] + ig * gg;
                            cst[mi][rh][j] = cc;
                            float h = og * tanhf(cc);
                            ep[(size_t)b * HH + n] = __float2half(h);
                            h1n[(size_t)b * HH + n] = rna_tf32(h);
                            if (s == LL) g_c1f[(size_t)b * HH + n] = cc;
                        }
                    }
            }
        }
        gridbar(&g_bar_enc, round, NBE);
    }
}

// ==================== DECODER ====================
__device__ __forceinline__ float dot8r(uint4 v, const float* s) {
    const __half2* h2 = (const __half2*)&v;
    float r = 0.f;
#pragma unroll
    for (int i = 0; i < 4; i++) {
        float2 f = __half22float2(h2[i]);
        r += f.x * s[2 * i] + f.y * s[2 * i + 1];
    }
    return r;
}

__device__ void attn_one(int ds, int b, bool full, const float* __restrict__ Wfc,
                         const float* __restrict__ bfc, float* __restrict__ out,
                         float* pa, float* pms) {
    int tid = threadIdx.x, lane = tid & 31, w = tid >> 5;
    const float* hd = g_h1[ds & 1] + (size_t)b * HH;
    float hreg[16];
#pragma unroll
    for (int i = 0; i < 8; i++) {
        hreg[i]     = hd[lane * 8 + i];
        hreg[8 + i] = hd[256 + lane * 8 + i];
    }
    if (w == 0) {   // y = h . Wfc + b
        float yv = 0.f;
#pragma unroll
        for (int i = 0; i < 8; i++)
            yv += hreg[i] * Wfc[lane * 8 + i] + hreg[8 + i] * Wfc[256 + lane * 8 + i];
#pragma unroll
        for (int off = 16; off; off >>= 1) yv += __shfl_xor_sync(0xffffffffu, yv, off);
        if (lane == 0) {
            float y = yv + bfc[0];
            if (ds > 0) out[b * PL + ds - 1] = y;
            g_yprev[b] = (ds == 0) ? 0.f : y;
        }
    }
    if (!full) return;

    // single-pass online softmax + context
    float M = -1e30f, S = 0.f, C[16];
#pragma unroll
    for (int i = 0; i < 16; i++) C[i] = 0.f;
    for (int l = w; l < LL; l += 8) {
        const uint4* e4 = (const uint4*)(g_enc + ((size_t)l * BB + b) * HH);
        uint4 v0 = e4[lane];
        uint4 v1 = e4[lane + 32];
        float s1 = dot8r(v0, hreg) + dot8r(v1, hreg + 8);
#pragma unroll
        for (int off = 16; off; off >>= 1) s1 += __shfl_xor_sync(0xffffffffu, s1, off);
        float mn = fmaxf(M, s1);
        float r = __expf(M - mn);
        float e = __expf(s1 - mn);
        S = S * r + e;
        const __half2* ha = (const __half2*)&v0;
        const __half2* hb = (const __half2*)&v1;
#pragma unroll
        for (int i = 0; i < 4; i++) {
            float2 f = __half22float2(ha[i]);
            C[2 * i]     = C[2 * i] * r + e * f.x;
            C[2 * i + 1] = C[2 * i + 1] * r + e * f.y;
            float2 f2 = __half22float2(hb[i]);
            C[8 + 2 * i]     = C[8 + 2 * i] * r + e * f2.x;
            C[8 + 2 * i + 1] = C[8 + 2 * i + 1] * r + e * f2.y;
        }
        M = mn;
    }
    if (lane == 0) { pms[w * 2] = M; pms[w * 2 + 1] = S; }
#pragma unroll
    for (int i = 0; i < 8; i++) {
        pa[w * 512 + lane * 8 + i]       = C[i];
        pa[w * 512 + 256 + lane * 8 + i] = C[8 + i];
    }
    __syncthreads();
    float Mg = -1e30f;
#pragma unroll
    for (int ww = 0; ww < 8; ww++) Mg = fmaxf(Mg, pms[ww * 2]);
    float Sg = 0.f;
    float scl[8];
#pragma unroll
    for (int ww = 0; ww < 8; ww++) {
        scl[ww] = __expf(pms[ww * 2] - Mg);
        Sg += pms[ww * 2 + 1] * scl[ww];
    }
    float inv = 1.f / Sg;
    for (int h = tid; h < HH; h += 256) {
        float a = 0.f;
#pragma unroll
        for (int ww = 0; ww < 8; ww++) a += pa[ww * 512 + h] * scl[ww];
        g_ctx[(size_t)b * HH + h] = rna_tf32(a * inv);
    }
    __syncthreads();
}

__global__ void __launch_bounds__(256, 1) dec_persistent(
    const float* __restrict__ Wdi, const float* __restrict__ Wdh,
    const float* __restrict__ bdi, const float* __restrict__ bdh,
    const float* __restrict__ Wfc, const float* __restrict__ bfc,
    float* __restrict__ out) {
    extern __shared__ float sm[];
    float* Ws   = sm;            // 16448
    float* As   = sm + 16448;    // 18432
    float* pa   = sm + 34880;    // 4096
    float* pms  = sm + 38976;    // 16
    float* bias = sm + 38992;    // 16
    float* wd0  = sm + 39008;    // 16
    int bx = blockIdx.x, tid = threadIdx.x;
    int lane = tid & 31, wid = tid >> 5, lr = lane >> 2, lc = lane & 3;
    int wbase = wid * 32;
    int nbase = bx * 4;

    for (int c = wid; c < 16; c += 8) {
        int gq = (c & 1) | ((c >> 2) & 2);
        int dn = (c >> 1) & 3;
        int row = gq * HH + nbase + dn;
        for (int k = lane; k < HH; k += 32) {
            Ws[c * 1028 + k]      = rna_tf32(Wdi[(size_t)row * (HH + 1) + 1 + k]);
            Ws[c * 1028 + HH + k] = rna_tf32(Wdh[(size_t)row * HH + k]);
        }
        if (lane == 0) {
            bias[c] = bdi[row] + bdh[row];
            wd0[c]  = Wdi[(size_t)row * (HH + 1)];
        }
    }
    float cst[2][2];
#pragma unroll
    for (int mi = 0; mi < 2; mi++)
#pragma unroll
        for (int rh = 0; rh < 2; rh++) {
            int b = wbase + mi * 16 + rh * 8 + lr;
            cst[mi][rh] = g_c1f[(size_t)b * HH + nbase + lc];
        }
    __syncthreads();

    unsigned round = 0;
    for (int ds = 0; ds <= PL; ds++) {
        attn_one(ds, bx, ds < PL, Wfc, bfc, out, pa, pms);
        attn_one(ds, bx + 128, ds < PL, Wfc, bfc, out, pa, pms);
        if (ds == PL) break;
        gridbar(&g_bar_dec, round, NBD);

        float acc[2][2][4];
#pragma unroll
        for (int a = 0; a < 2; a++)
#pragma unroll
            for (int b = 0; b < 2; b++)
#pragma unroll
                for (int q = 0; q < 4; q++) acc[a][b][q] = 0.f;
        gemm_K<2, 32>(g_ctx, g_h1[ds & 1], As, Ws, 1028, acc, wbase, lr, lc);
        float* h1n = g_h1[(ds + 1) & 1];
#pragma unroll
        for (int mi = 0; mi < 2; mi++)
#pragma unroll
            for (int rh = 0; rh < 2; rh++) {
                int b = wbase + mi * 16 + rh * 8 + lr;
                float y = g_yprev[b];
                int n = nbase + lc;
                float gv[4];
#pragma unroll
                for (int gq = 0; gq < 4; gq++) {
                    int ni = gq >> 1;
                    int cix = ni * 8 + 2 * lc + (gq & 1);
                    gv[gq] = acc[mi][ni][rh * 2 + (gq & 1)] + bias[cix] + wd0[cix] * y;
                }
                float ig = sigf(gv[0]), fg = sigf(gv[1]);
                float gg = tanhf(gv[2]), og = sigf(gv[3]);
                float cc = fg * cst[mi][rh] + ig * gg;
                cst[mi][rh] = cc;
                h1n[(size_t)b * HH + n] = rna_tf32(og * tanhf(cc));
            }
        gridbar(&g_bar_dec, round, NBD);
    }
}

extern "C" void kernel_launch(void* const* d_in, const int* in_sizes, int n_in,
                              void* d_out, int out_size) {
    const float* x    = (const float*)d_in[0];
    const float* Wih0 = (const float*)d_in[1];
    const float* Whh0 = (const float*)d_in[2];
    const float* bi0  = (const float*)d_in[3];
    const float* bh0  = (const float*)d_in[4];
    const float* Wih1 = (const float*)d_in[5];
    const float* Whh1 = (const float*)d_in[6];
    const float* bi1  = (const float*)d_in[7];
    const float* bh1  = (const float*)d_in[8];
    const float* Wdi  = (const float*)d_in[9];
    const float* Wdh  = (const float*)d_in[10];
    const float* bdi  = (const float*)d_in[11];
    const float* bdh  = (const float*)d_in[12];
    const float* Wfc  = (const float*)d_in[13];
    const float* bfc  = (const float*)d_in[14];
    float* out = (float*)d_out;

    static bool attr_done = false;
    if (!attr_done) {
        cudaFuncSetAttribute(enc_persistent, cudaFuncAttributeMaxDynamicSharedMemorySize, 217344);
        cudaFuncSetAttribute(dec_persistent, cudaFuncAttributeMaxDynamicSharedMemorySize, 156096);
        attr_done = true;
    }

    prep_kernel<<<(BB * HH + 255) / 256, 256>>>();
    enc_persistent<<<NBE, 256, 217344>>>(x, Wih0, Whh0, Wih1, Whh1, bi0, bh0, bi1, bh1);
    dec_persistent<<<NBD, 256, 156096>>>(Wdi, Wdh, bdi, bdh, Wfc, bfc, out);
}

// round 5
// speedup vs baseline: 2.2463x; 2.2463x over previous
#include <cuda_runtime.h>
#include <cuda_fp16.h>
#include <stdint.h>

#define BB 256
#define LL 336
#define NIN 8
#define HH 512
#define PL 96
#define NBE 96
#define NBD 128

__device__ __half g_h0[2][BB*HH];
__device__ __half g_h1[2][BB*HH];
__device__ float  g_c1f[BB*HH];
__device__ __half g_ctx[BB*HH];
__device__ float  g_yprev[BB];
__device__ __half g_enc[(size_t)LL*BB*HH];
__device__ unsigned g_bar_enc, g_bar_dec;

__device__ __forceinline__ float sigf(float x) { return 1.f / (1.f + __expf(-x)); }

__device__ __forceinline__ void gridbar(unsigned* bar, unsigned& round, unsigned nblk) {
    round++;
    __syncthreads();
    __threadfence();
    if (threadIdx.x == 0) {
        unsigned target = round * nblk;
        atomicAdd(bar, 1u);
        while (*(volatile unsigned*)bar < target) { }
        __threadfence();
    }
    __syncthreads();
}

__device__ __forceinline__ void mma16(float c[4], const uint32_t a[4], const uint32_t b[2]) {
    asm volatile(
        "mma.sync.aligned.m16n8k16.row.col.f32.f16.f16.f32 "
        "{%0,%1,%2,%3},{%4,%5,%6,%7},{%8,%9},{%0,%1,%2,%3};"
        : "+f"(c[0]), "+f"(c[1]), "+f"(c[2]), "+f"(c[3])
        : "r"(a[0]), "r"(a[1]), "r"(a[2]), "r"(a[3]), "r"(b[0]), "r"(b[1]));
}

#define CP_COMMIT asm volatile("cp.async.commit_group;\n")
#define CP_WAIT1  asm volatile("cp.async.wait_group 1;\n")
#define CP_WAIT0  asm volatile("cp.async.wait_group 0;\n")

// stage a 128-row x 64-half K-chunk into smem (stride 72 halves)
__device__ __forceinline__ void stage64(__half* dst, const __half* __restrict__ src) {
    int t = threadIdx.x;
    int row = t >> 1;
    int off = (t & 1) * 32;
    const __half* g = src + (size_t)row * HH + off;
    unsigned sa = (unsigned)__cvta_generic_to_shared(dst + row * 72 + off);
#pragma unroll
    for (int i = 0; i < 4; i++)
        asm volatile("cp.async.cg.shared.global [%0], [%1], 16;\n"
                     :: "r"(sa + i * 16), "l"(g + i * 8));
}

// C[128, NT*8*2warps] += A[128,K] * W^T  (fp16 mma, W in smem, A streamed)
template<int NT, int NCH, int KPAD>
__device__ __forceinline__ void gemm16(const __half* __restrict__ srcA,
                                       const __half* __restrict__ srcB,
                                       __half* As, const __half* Ws,
                                       float (&acc)[2][NT][4],
                                       int wm, int wn, int lr, int lc2) {
    const __half* s0 = srcA;
    stage64(As, s0);
    CP_COMMIT;
    const __half* Wp = Ws + (size_t)(wn * NT * 8 + lr) * KPAD + lc2;
    for (int kc = 0; kc < NCH; kc++) {
        if (kc + 1 < NCH) {
            int ko = (kc + 1) * 64;
            const __half* s = (srcB == nullptr || ko < HH) ? srcA + ko : srcB + (ko - HH);
            stage64(As + ((kc + 1) & 1) * (128 * 72), s);
            CP_COMMIT; CP_WAIT1;
        } else {
            CP_WAIT0;
        }
        __syncthreads();
        const __half* Ab = As + (kc & 1) * (128 * 72) + (size_t)(wm * 32 + lr) * 72 + lc2;
        int kb = kc * 64;
#pragma unroll
        for (int ko = 0; ko < 64; ko += 16) {
            uint32_t a[2][4], b[NT][2];
#pragma unroll
            for (int mi = 0; mi < 2; mi++) {
                const __half* ap = Ab + mi * 16 * 72 + ko;
                a[mi][0] = *(const uint32_t*)(ap);
                a[mi][1] = *(const uint32_t*)(ap + 8 * 72);
                a[mi][2] = *(const uint32_t*)(ap + 8);
                a[mi][3] = *(const uint32_t*)(ap + 8 * 72 + 8);
            }
#pragma unroll
            for (int ni = 0; ni < NT; ni++) {
                const __half* bp = Wp + (size_t)ni * 8 * KPAD + kb + ko;
                b[ni][0] = *(const uint32_t*)(bp);
                b[ni][1] = *(const uint32_t*)(bp + 8);
            }
#pragma unroll
            for (int mi = 0; mi < 2; mi++)
#pragma unroll
                for (int ni = 0; ni < NT; ni++)
                    mma16(acc[mi][ni], a[mi], b[ni]);
        }
        __syncthreads();
    }
}

__global__ void prep_kernel() {
    int i = blockIdx.x * blockDim.x + threadIdx.x;
    if (i < BB * HH) {
        g_h0[0][i] = __float2half(0.f);
        g_h1[0][i] = __float2half(0.f);
    }
    if (i == 0) { g_bar_enc = 0u; g_bar_dec = 0u; }
}

// ==================== ENCODER ====================
// 32 L0 CTAs (2M x 16N, 128 gate-cols, K=512) + 64 L1 CTAs (2M x 32N, 64 cols, K=1024)
__global__ void __launch_bounds__(256, 1) enc_persistent(
    const float* __restrict__ x, const float* __restrict__ Wih0,
    const float* __restrict__ Whh0, const float* __restrict__ Wih1,
    const float* __restrict__ Whh1,
    const float* __restrict__ bi0, const float* __restrict__ bh0,
    const float* __restrict__ bi1, const float* __restrict__ bh1) {
    extern __shared__ __half smh[];
    __half* Ws = smh;                 // up to 66560 halves
    __half* As = smh + 66560;         // 18432 halves (dbl buf)
    float* fb  = (float*)(smh + 66560 + 18432);
    float* xs   = fb;                 // 1152
    float* bias = fb + 1152;          // 128
    float* w0x  = fb + 1280;          // 1024

    int bx = blockIdx.x, tid = threadIdx.x;
    int lane = tid & 31, wid = tid >> 5;
    int lr = lane >> 2, lc = lane & 3, lc2 = lc * 2;
    int wm = wid >> 1, wn = wid & 1;
    bool L0 = bx < 32;
    int cid = L0 ? bx : bx - 32;
    int mh = cid & 1;
    int nblk = cid >> 1;
    int nbase = L0 ? nblk * 32 : nblk * 16;
    int ncols = L0 ? 128 : 64;

    // ---- load weights into smem (fp16), permuted so each lane owns all 4 gates ----
    for (int cc = wid; cc < ncols; cc += 8) {
        int gq = (cc & 1) | ((cc >> 2) & 2);
        int dn = ((cc >> 1) & 3) | ((cc >> 4) << 2);
        int row = gq * HH + nbase + dn;
        if (L0) {
            for (int k = lane * 4; k < HH; k += 128) {
                float4 w = *(const float4*)(Whh0 + (size_t)row * HH + k);
                __half* d = Ws + (size_t)cc * 520 + k;
                d[0] = __float2half(w.x); d[1] = __float2half(w.y);
                d[2] = __float2half(w.z); d[3] = __float2half(w.w);
            }
            if (lane < 8) w0x[cc * 8 + lane] = Wih0[row * NIN + lane];
            if (lane == 0) bias[cc] = bi0[row] + bh0[row];
        } else {
            for (int k = lane * 4; k < HH; k += 128) {
                float4 wa = *(const float4*)(Wih1 + (size_t)row * HH + k);
                float4 wb = *(const float4*)(Whh1 + (size_t)row * HH + k);
                __half* d = Ws + (size_t)cc * 1032 + k;
                d[0] = __float2half(wa.x); d[1] = __float2half(wa.y);
                d[2] = __float2half(wa.z); d[3] = __float2half(wa.w);
                __half* d2 = d + HH;
                d2[0] = __float2half(wb.x); d2[1] = __float2half(wb.y);
                d2[2] = __float2half(wb.z); d2[3] = __float2half(wb.w);
            }
            if (lane == 0) bias[cc] = bi1[row] + bh1[row];
        }
    }
    float cst[2][2][4];
#pragma unroll
    for (int a = 0; a < 2; a++)
#pragma unroll
        for (int b = 0; b < 2; b++)
#pragma unroll
            for (int q = 0; q < 4; q++) cst[a][b][q] = 0.f;
    __syncthreads();

    unsigned round = 0;
    for (int s = 0; s <= LL; s++) {
        if (L0) {
            if (s < LL) {
                if (tid < 128) {
                    const float* xp = x + ((size_t)(mh * 128 + tid) * LL + s) * NIN;
#pragma unroll
                    for (int k = 0; k < 8; k++) xs[tid * 9 + k] = xp[k];
                }
                float acc[2][8][4];
#pragma unroll
                for (int a = 0; a < 2; a++)
#pragma unroll
                    for (int b = 0; b < 8; b++)
#pragma unroll
                        for (int q = 0; q < 4; q++) acc[a][b][q] = 0.f;
                gemm16<8, 8, 520>(g_h0[s & 1] + (size_t)mh * 128 * HH, nullptr,
                                  As, Ws, acc, wm, wn, lr, lc2);
                __half* h0n = g_h0[(s + 1) & 1];
#pragma unroll
                for (int mi = 0; mi < 2; mi++)
#pragma unroll
                    for (int rh = 0; rh < 2; rh++) {
                        int rloc = wm * 32 + mi * 16 + rh * 8 + lr;
                        int b = mh * 128 + rloc;
                        const float* xr = xs + rloc * 9;
#pragma unroll
                        for (int j = 0; j < 4; j++) {
                            int n = nbase + lc + 4 * j + 16 * wn;
                            float gv[4];
#pragma unroll
                            for (int gq = 0; gq < 4; gq++) {
                                int ni = 2 * j + (gq >> 1);
                                int cc = wn * 64 + ni * 8 + lc2 + (gq & 1);
                                float a = acc[mi][ni][rh * 2 + (gq & 1)] + bias[cc];
                                const float* wr = w0x + cc * 8;
#pragma unroll
                                for (int k = 0; k < 8; k++) a += wr[k] * xr[k];
                                gv[gq] = a;
                            }
                            float ig = sigf(gv[0]), fg = sigf(gv[1]);
                            float gg = tanhf(gv[2]), og = sigf(gv[3]);
                            float cv = fg * cst[mi][rh][j] + ig * gg;
                            cst[mi][rh][j] = cv;
                            h0n[(size_t)b * HH + n] = __float2half(og * tanhf(cv));
                        }
                    }
            }
        } else {
            if (s >= 1) {
                float acc[2][4][4];
#pragma unroll
                for (int a = 0; a < 2; a++)
#pragma unroll
                    for (int b = 0; b < 4; b++)
#pragma unroll
                        for (int q = 0; q < 4; q++) acc[a][b][q] = 0.f;
                gemm16<4, 16, 1032>(g_h0[s & 1] + (size_t)mh * 128 * HH,
                                    g_h1[(s + 1) & 1] + (size_t)mh * 128 * HH,
                                    As, Ws, acc, wm, wn, lr, lc2);
                __half* h1n = g_h1[s & 1];
                __half* ep = g_enc + (size_t)(s - 1) * BB * HH;
#pragma unroll
                for (int mi = 0; mi < 2; mi++)
#pragma unroll
                    for (int rh = 0; rh < 2; rh++) {
                        int b = mh * 128 + wm * 32 + mi * 16 + rh * 8 + lr;
#pragma unroll
                        for (int j = 0; j < 2; j++) {
                            int n = nbase + lc + 4 * j + 8 * wn;
                            float gv[4];
#pragma unroll
                            for (int gq = 0; gq < 4; gq++) {
                                int ni = 2 * j + (gq >> 1);
                                int cc = wn * 32 + ni * 8 + lc2 + (gq & 1);
                                gv[gq] = acc[mi][ni][rh * 2 + (gq & 1)] + bias[cc];
                            }
                            float ig = sigf(gv[0]), fg = sigf(gv[1]);
                            float gg = tanhf(gv[2]), og = sigf(gv[3]);
                            float cv = fg * cst[mi][rh][j] + ig * gg;
                            cst[mi][rh][j] = cv;
                            __half h16 = __float2half(og * tanhf(cv));
                            ep[(size_t)b * HH + n] = h16;
                            h1n[(size_t)b * HH + n] = h16;
                            if (s == LL) g_c1f[(size_t)b * HH + n] = cv;
                        }
                    }
            }
        }
        gridbar(&g_bar_enc, round, NBE);
    }
}

// ==================== DECODER ====================
__device__ __forceinline__ float dot8r(uint4 v, const float* s) {
    const __half2* h2 = (const __half2*)&v;
    float r = 0.f;
#pragma unroll
    for (int i = 0; i < 4; i++) {
        float2 f = __half22float2(h2[i]);
        r += f.x * s[2 * i] + f.y * s[2 * i + 1];
    }
    return r;
}

__device__ void attn_one(int ds, int b, bool full, const float* __restrict__ Wfc,
                         const float* __restrict__ bfc, float* __restrict__ out,
                         float* pa, float* pms) {
    int tid = threadIdx.x, lane = tid & 31, w = tid >> 5;
    const __half* hd = g_h1[ds & 1] + (size_t)b * HH;
    float hreg[16];
#pragma unroll
    for (int i = 0; i < 8; i++) {
        hreg[i]     = __half2float(hd[lane * 8 + i]);
        hreg[8 + i] = __half2float(hd[256 + lane * 8 + i]);
    }
    if (w == 0) {
        float yv = 0.f;
#pragma unroll
        for (int i = 0; i < 8; i++)
            yv += hreg[i] * Wfc[lane * 8 + i] + hreg[8 + i] * Wfc[256 + lane * 8 + i];
#pragma unroll
        for (int off = 16; off; off >>= 1) yv += __shfl_xor_sync(0xffffffffu, yv, off);
        if (lane == 0) {
            float y = yv + bfc[0];
            if (ds > 0) out[b * PL + ds - 1] = y;
            g_yprev[b] = (ds == 0) ? 0.f : y;
        }
    }
    if (!full) return;

    float M = -1e30f, S = 0.f, C[16];
#pragma unroll
    for (int i = 0; i < 16; i++) C[i] = 0.f;
    for (int l = w; l < LL; l += 8) {
        const uint4* e4 = (const uint4*)(g_enc + ((size_t)l * BB + b) * HH);
        uint4 v0 = e4[lane];
        uint4 v1 = e4[lane + 32];
        float s1 = dot8r(v0, hreg) + dot8r(v1, hreg + 8);
#pragma unroll
        for (int off = 16; off; off >>= 1) s1 += __shfl_xor_sync(0xffffffffu, s1, off);
        float mn = fmaxf(M, s1);
        float r = __expf(M - mn);
        float e = __expf(s1 - mn);
        S = S * r + e;
        const __half2* ha = (const __half2*)&v0;
        const __half2* hb = (const __half2*)&v1;
#pragma unroll
        for (int i = 0; i < 4; i++) {
            float2 f = __half22float2(ha[i]);
            C[2 * i]     = C[2 * i] * r + e * f.x;
            C[2 * i + 1] = C[2 * i + 1] * r + e * f.y;
            float2 f2 = __half22float2(hb[i]);
            C[8 + 2 * i]     = C[8 + 2 * i] * r + e * f2.x;
            C[8 + 2 * i + 1] = C[8 + 2 * i + 1] * r + e * f2.y;
        }
        M = mn;
    }
    if (lane == 0) { pms[w * 2] = M; pms[w * 2 + 1] = S; }
#pragma unroll
    for (int i = 0; i < 8; i++) {
        pa[w * 512 + lane * 8 + i]       = C[i];
        pa[w * 512 + 256 + lane * 8 + i] = C[8 + i];
    }
    __syncthreads();
    float Mg = -1e30f;
#pragma unroll
    for (int ww = 0; ww < 8; ww++) Mg = fmaxf(Mg, pms[ww * 2]);
    float Sg = 0.f;
    float scl[8];
#pragma unroll
    for (int ww = 0; ww < 8; ww++) {
        scl[ww] = __expf(pms[ww * 2] - Mg);
        Sg += pms[ww * 2 + 1] * scl[ww];
    }
    float inv = 1.f / Sg;
    for (int h = tid; h < HH; h += 256) {
        float a = 0.f;
#pragma unroll
        for (int ww = 0; ww < 8; ww++) a += pa[ww * 512 + h] * scl[ww];
        g_ctx[(size_t)b * HH + h] = __float2half(a * inv);
    }
    __syncthreads();
}

// 128 CTAs: 2M x 64N (8 hidden each); attention for 2 batches per CTA
__global__ void __launch_bounds__(256, 1) dec_persistent(
    const float* __restrict__ Wdi, const float* __restrict__ Wdh,
    const float* __restrict__ bdi, const float* __restrict__ bdh,
    const float* __restrict__ Wfc, const float* __restrict__ bfc,
    float* __restrict__ out) {
    extern __shared__ __half smh[];
    __half* Ws = smh;                 // 33024 halves
    __half* As = smh + 33024;         // 18432 halves
    float* fb  = (float*)(smh + 33024 + 18432);
    float* pa   = fb;                 // 4096
    float* pms  = fb + 4096;          // 16
    float* bias = fb + 4112;          // 32
    float* wd0  = fb + 4144;          // 32

    int bx = blockIdx.x, tid = threadIdx.x;
    int lane = tid & 31, wid = tid >> 5;
    int lr = lane >> 2, lc = lane & 3, lc2 = lc * 2;
    int wm = wid >> 1, wn = wid & 1;
    int mh = bx & 1;
    int nbase = (bx >> 1) * 8;

    for (int cc = wid; cc < 32; cc += 8) {
        int gq = (cc & 1) | ((cc >> 2) & 2);
        int dn = ((cc >> 1) & 3) | ((cc >> 4) << 2);
        int row = gq * HH + nbase + dn;
        for (int k = lane; k < HH; k += 32) {
            Ws[(size_t)cc * 1032 + k]      = __float2half(Wdi[(size_t)row * (HH + 1) + 1 + k]);
            Ws[(size_t)cc * 1032 + HH + k] = __float2half(Wdh[(size_t)row * HH + k]);
        }
        if (lane == 0) {
            bias[cc] = bdi[row] + bdh[row];
            wd0[cc]  = Wdi[(size_t)row * (HH + 1)];
        }
    }
    float cst[2][2];
#pragma unroll
    for (int mi = 0; mi < 2; mi++)
#pragma unroll
        for (int rh = 0; rh < 2; rh++) {
            int b = mh * 128 + wm * 32 + mi * 16 + rh * 8 + lr;
            int n = nbase + lc + 4 * wn;
            cst[mi][rh] = g_c1f[(size_t)b * HH + n];
        }
    __syncthreads();

    unsigned round = 0;
    for (int ds = 0; ds <= PL; ds++) {
        attn_one(ds, bx, ds < PL, Wfc, bfc, out, pa, pms);
        attn_one(ds, bx + 128, ds < PL, Wfc, bfc, out, pa, pms);
        if (ds == PL) break;
        gridbar(&g_bar_dec, round, NBD);

        float acc[2][2][4];
#pragma unroll
        for (int a = 0; a < 2; a++)
#pragma unroll
            for (int b = 0; b < 2; b++)
#pragma unroll
                for (int q = 0; q < 4; q++) acc[a][b][q] = 0.f;
        gemm16<2, 16, 1032>(g_ctx + (size_t)mh * 128 * HH,
                            g_h1[ds & 1] + (size_t)mh * 128 * HH,
                            As, Ws, acc, wm, wn, lr, lc2);
        __half* h1n = g_h1[(ds + 1) & 1];
#pragma unroll
        for (int mi = 0; mi < 2; mi++)
#pragma unroll
            for (int rh = 0; rh < 2; rh++) {
                int b = mh * 128 + wm * 32 + mi * 16 + rh * 8 + lr;
                float y = g_yprev[b];
                int n = nbase + lc + 4 * wn;
                float gv[4];
#pragma unroll
                for (int gq = 0; gq < 4; gq++) {
                    int ni = gq >> 1;
                    int cc = wn * 16 + ni * 8 + lc2 + (gq & 1);
                    gv[gq] = acc[mi][ni][rh * 2 + (gq & 1)] + bias[cc] + wd0[cc] * y;
                }
                float ig = sigf(gv[0]), fg = sigf(gv[1]);
                float gg = tanhf(gv[2]), og = sigf(gv[3]);
                float cv = fg * cst[mi][rh] + ig * gg;
                cst[mi][rh] = cv;
                h1n[(size_t)b * HH + n] = __float2half(og * tanhf(cv));
            }
        gridbar(&g_bar_dec, round, NBD);
    }
}

extern "C" void kernel_launch(void* const* d_in, const int* in_sizes, int n_in,
                              void* d_out, int out_size) {
    const float* x    = (const float*)d_in[0];
    const float* Wih0 = (const float*)d_in[1];
    const float* Whh0 = (const float*)d_in[2];
    const float* bi0  = (const float*)d_in[3];
    const float* bh0  = (const float*)d_in[4];
    const float* Wih1 = (const float*)d_in[5];
    const float* Whh1 = (const float*)d_in[6];
    const float* bi1  = (const float*)d_in[7];
    const float* bh1  = (const float*)d_in[8];
    const float* Wdi  = (const float*)d_in[9];
    const float* Wdh  = (const float*)d_in[10];
    const float* bdi  = (const float*)d_in[11];
    const float* bdh  = (const float*)d_in[12];
    const float* Wfc  = (const float*)d_in[13];
    const float* bfc  = (const float*)d_in[14];
    float* out = (float*)d_out;

    cudaFuncSetAttribute(enc_persistent, cudaFuncAttributeMaxDynamicSharedMemorySize, 179200);
    cudaFuncSetAttribute(dec_persistent, cudaFuncAttributeMaxDynamicSharedMemorySize, 119616);

    prep_kernel<<<(BB * HH + 255) / 256, 256>>>();
    enc_persistent<<<NBE, 256, 179200>>>(x, Wih0, Whh0, Wih1, Whh1, bi0, bh0, bi1, bh1);
    dec_persistent<<<NBD, 256, 119616>>>(Wdi, Wdh, bdi, bdh, Wfc, bfc, out);
}